// round 1
// baseline (speedup 1.0000x reference)
#include <cuda_runtime.h>
#include <cuda_bf16.h>

// Problem constants
#define NROWS 65536
#define DDIM  256
#define KCODES 4096
#define BM 128          // rows per block
#define BK 64           // codes per chunk
#define QTZ_BETA 0.25

// Scratch (device globals: allocation-free rule)
__device__ float  g_zT[DDIM * NROWS];    // [d][row]  64MB
__device__ float  g_cbT[DDIM * KCODES];  // [d][code]  4MB
__device__ float  g_cnorm[KCODES];
__device__ double g_loss;

// ---------------- f32x2 helpers ----------------
__device__ __forceinline__ unsigned long long pack2(float a, float b) {
    unsigned long long r;
    asm("mov.b64 %0, {%1, %2};" : "=l"(r) : "f"(a), "f"(b));
    return r;
}
__device__ __forceinline__ void unpack2(unsigned long long p, float& a, float& b) {
    asm("mov.b64 {%0, %1}, %2;" : "=f"(a), "=f"(b) : "l"(p));
}
__device__ __forceinline__ void ffma2(unsigned long long& d,
                                      unsigned long long a,
                                      unsigned long long b) {
    asm("fma.rn.f32x2 %0, %1, %2, %0;" : "+l"(d) : "l"(a), "l"(b));
}

// ---------------- transpose (32x32 tiles) ----------------
__device__ __forceinline__ void transpose_body(const float* __restrict__ in,
                                               float* __restrict__ out,
                                               int nrows, int ncols) {
    __shared__ float tile[32][33];
    int c0 = blockIdx.x * 32;
    int r0 = blockIdx.y * 32;
    #pragma unroll
    for (int i = 0; i < 32; i += 8)
        tile[threadIdx.y + i][threadIdx.x] =
            in[(size_t)(r0 + threadIdx.y + i) * ncols + c0 + threadIdx.x];
    __syncthreads();
    #pragma unroll
    for (int i = 0; i < 32; i += 8)
        out[(size_t)(c0 + threadIdx.y + i) * nrows + r0 + threadIdx.x] =
            tile[threadIdx.x][threadIdx.y + i];
}

__global__ void transposeZ(const float* __restrict__ z) {
    transpose_body(z, g_zT, NROWS, DDIM);
}
__global__ void transposeCB(const float* __restrict__ cb) {
    transpose_body(cb, g_cbT, KCODES, DDIM);
}

// ---------------- codebook norms + loss zero ----------------
__global__ void cnorm_kernel(const float* __restrict__ cb) {
    int j = blockIdx.x;
    const float4 v = *(const float4*)(cb + (size_t)j * DDIM + threadIdx.x * 4);
    float s = v.x * v.x + v.y * v.y + v.z * v.z + v.w * v.w;
    #pragma unroll
    for (int o = 16; o > 0; o >>= 1) s += __shfl_down_sync(0xffffffffu, s, o);
    __shared__ float ws[2];
    if ((threadIdx.x & 31) == 0) ws[threadIdx.x >> 5] = s;
    __syncthreads();
    if (threadIdx.x == 0) {
        g_cnorm[j] = ws[0] + ws[1];
        if (j == 0) g_loss = 0.0;
    }
}

// ---------------- main VQ kernel ----------------
// smem layout (floats): sZ[256*128] | sC[256*64] | sNorm[128] | sIds[128]
// reduction arrays alias sC after the mainloop.
#define SMEM_FLOATS (DDIM * BM + DDIM * BK + BM + BM)

__global__ __launch_bounds__(256, 1)
void vq_main(const float* __restrict__ cb,
             float* __restrict__ zq_out,
             float* __restrict__ ids_out) {
    extern __shared__ float smem[];
    float* sZ    = smem;                       // [d][row] 128 wide
    float* sC    = smem + DDIM * BM;           // [d][code] 64 wide
    float* sNorm = sC + DDIM * BK;             // [128]
    int*   sIds  = (int*)(sNorm + BM);         // [128]

    const int tid = threadIdx.x;
    const int tx = tid & 15;       // code group (4 codes)
    const int ty = tid >> 4;       // row group (8 rows)
    const int rowBase = blockIdx.x * BM;

    // ---- fill sZ from g_zT (coalesced, conflict-free) ----
    #pragma unroll
    for (int i = 0; i < 32; i++) {
        int f = i * 256 + tid;                 // 8192 float4s
        int d = f >> 5;
        int c4 = (f & 31) << 2;
        *(float4*)(sZ + d * BM + c4) =
            *(const float4*)(g_zT + (size_t)d * NROWS + rowBase + c4);
    }
    __syncthreads();

    // ---- per-row ||z||^2 (needed only for loss) ----
    if (tid < BM) {
        float s = 0.f;
        #pragma unroll 4
        for (int d = 0; d < DDIM; d++) {
            float v = sZ[d * BM + tid];
            s += v * v;
        }
        sNorm[tid] = s;
    }

    float minv[8];
    int   mini[8];
    #pragma unroll
    for (int k = 0; k < 8; k++) { minv[k] = 3.4e38f; mini[k] = 0; }

    for (int kb = 0; kb < KCODES; kb += BK) {
        __syncthreads();
        // ---- fill sC chunk from g_cbT ----
        #pragma unroll
        for (int i = 0; i < 16; i++) {
            int f = i * 256 + tid;             // 4096 float4s
            int d = f >> 4;
            int c4 = (f & 15) << 2;
            *(float4*)(sC + d * BK + c4) =
                *(const float4*)(g_cbT + (size_t)d * KCODES + kb + c4);
        }
        __syncthreads();

        unsigned long long acc[4][4];
        #pragma unroll
        for (int p = 0; p < 4; p++)
            #pragma unroll
            for (int c = 0; c < 4; c++) acc[p][c] = 0ull;

        const float* zp = sZ + 8 * ty;
        const float* cp = sC + 4 * tx;

        #pragma unroll 2
        for (int d = 0; d < DDIM; d++) {
            float4 za = *(const float4*)(zp);
            float4 zb = *(const float4*)(zp + 4);
            float4 cq = *(const float4*)(cp);
            zp += BM; cp += BK;

            unsigned long long zpair[4];
            zpair[0] = pack2(za.x, za.y);
            zpair[1] = pack2(za.z, za.w);
            zpair[2] = pack2(zb.x, zb.y);
            zpair[3] = pack2(zb.z, zb.w);
            unsigned long long cdup[4];
            cdup[0] = pack2(cq.x, cq.x);
            cdup[1] = pack2(cq.y, cq.y);
            cdup[2] = pack2(cq.z, cq.z);
            cdup[3] = pack2(cq.w, cq.w);

            #pragma unroll
            for (int p = 0; p < 4; p++)
                #pragma unroll
                for (int c = 0; c < 4; c++)
                    ffma2(acc[p][c], zpair[p], cdup[c]);
        }

        // ---- chunk epilogue: running argmin of (||c||^2 - 2 z.c) ----
        #pragma unroll
        for (int c = 0; c < 4; c++) {
            int j = kb + 4 * tx + c;
            float cn = __ldg(g_cnorm + j);
            #pragma unroll
            for (int p = 0; p < 4; p++) {
                float d0, d1;
                unpack2(acc[p][c], d0, d1);
                float e0 = cn - 2.f * d0;
                float e1 = cn - 2.f * d1;
                if (e0 < minv[2 * p])     { minv[2 * p]     = e0; mini[2 * p]     = j; }
                if (e1 < minv[2 * p + 1]) { minv[2 * p + 1] = e1; mini[2 * p + 1] = j; }
            }
        }
    }

    // ---- cross-lane reduction (16 tx candidates per row) ----
    __syncthreads();
    float* sRedV = sC;                     // [128][16]
    int*   sRedI = (int*)(sC + BM * 16);   // [128][16]
    #pragma unroll
    for (int k = 0; k < 8; k++) {
        int r = 8 * ty + k;
        sRedV[r * 16 + tx] = minv[k];
        sRedI[r * 16 + tx] = mini[k];
    }
    __syncthreads();

    if (tid < BM) {
        float bv = sRedV[tid * 16];
        int   bj = sRedI[tid * 16];
        #pragma unroll
        for (int e = 1; e < 16; e++) {
            float v = sRedV[tid * 16 + e];
            if (v < bv) { bv = v; bj = sRedI[tid * 16 + e]; }
        }
        sIds[tid] = bj;
        ids_out[rowBase + tid] = (float)bj;
        // rowLoss = min(-2 z.c + ||c||^2) + ||z||^2 = ||z - c*||^2
        sNorm[tid] = bv + sNorm[tid];
    }
    __syncthreads();

    if (tid == 0) {
        float s = 0.f;
        #pragma unroll 4
        for (int r = 0; r < BM; r++) s += sNorm[r];
        atomicAdd(&g_loss, (double)s);
    }

    // ---- gather z_q = codebook[id] ----
    int w = tid >> 5, l = tid & 31;
    for (int rr = w; rr < BM; rr += 8) {
        int id = sIds[rr];
        const float4* src = (const float4*)(cb + (size_t)id * DDIM);
        float4* dst = (float4*)(zq_out + (size_t)(rowBase + rr) * DDIM);
        dst[l]      = src[l];
        dst[l + 32] = src[l + 32];
    }
}

// ---------------- loss finalize ----------------
__global__ void finalize_kernel(float* __restrict__ loss_out) {
    *loss_out = (float)(g_loss * (1.0 + QTZ_BETA) / ((double)NROWS * (double)DDIM));
}

// ---------------- launch ----------------
extern "C" void kernel_launch(void* const* d_in, const int* in_sizes, int n_in,
                              void* d_out, int out_size) {
    const float* z  = (const float*)d_in[0];
    const float* cb = (const float*)d_in[1];
    float* out = (float*)d_out;

    float* zq_out   = out;                          // N*D
    float* loss_out = out + (size_t)NROWS * DDIM;   // 1
    float* ids_out  = loss_out + 1;                 // N

    static_assert(SMEM_FLOATS * 4 <= 227 * 1024, "smem");
    cudaFuncSetAttribute(vq_main, cudaFuncAttributeMaxDynamicSharedMemorySize,
                         SMEM_FLOATS * 4);

    dim3 tb(32, 8);
    transposeZ<<<dim3(DDIM / 32, NROWS / 32), tb>>>(z);
    transposeCB<<<dim3(DDIM / 32, KCODES / 32), tb>>>(cb);
    cnorm_kernel<<<KCODES, 64>>>(cb);
    vq_main<<<NROWS / BM, 256, SMEM_FLOATS * 4>>>(cb, zq_out, ids_out);
    finalize_kernel<<<1, 1>>>(loss_out);
}

// round 3
// speedup vs baseline: 1.2160x; 1.2160x over previous
#include <cuda_runtime.h>
#include <cuda_bf16.h>
#include <cstdint>

#define NROWS  65536
#define DDIM   256
#define KCODES 4096
#define QTZ_BETA 0.25
#define BM 128
#define BNC 128                   // codes per chunk
#define NCHUNK (KCODES / BNC)     // 32
#define KD 64                     // d-elements per stage
#define NKD (DDIM / KD)           // 4
#define NIT (NCHUNK * NKD)        // 128
#define NTERMS 6

// -------- device scratch (allocation-free rule) --------
__device__ __nv_bfloat16 g_zspl[3][NROWS][DDIM];   // 96MB
__device__ __nv_bfloat16 g_cbspl[3][KCODES][DDIM]; // 6MB
__device__ float  g_znorm[NROWS];
__device__ float  g_cnorm[KCODES];
__device__ double g_loss;

// -------- smem map (bytes) --------
#define SPLIT_B 16384             // 128 ents * 64 bf16 * 2B
#define STAGE_B (3 * SPLIT_B)     // 49152
#define OFF_ZS   0
#define OFF_CS   (2 * STAGE_B)            // 98304
#define OFF_CN   (4 * STAGE_B)            // 196608 (4096 floats)
#define OFF_REDV (OFF_CN + 16384)         // 212992 (128*4 floats)
#define OFF_REDI (OFF_REDV + 2048)        // 215040 (128*4 ints)
#define OFF_IDS  (OFF_REDI + 2048)        // 217088 (128 ints)
#define OFF_LOSS (OFF_IDS + 512)          // 217600 (4 floats)
#define SMEM_TOTAL (OFF_LOSS + 64)        // 217664

// ---------------- PTX helpers ----------------
__device__ __forceinline__ uint32_t smem_u32(const void* p) {
    uint32_t a;
    asm("{ .reg .u64 t; cvta.to.shared.u64 t, %1; cvt.u32.u64 %0, t; }" : "=r"(a) : "l"(p));
    return a;
}
__device__ __forceinline__ void cp_async16(uint32_t dst, const void* src) {
    asm volatile("cp.async.cg.shared.global [%0], [%1], 16;" :: "r"(dst), "l"(src) : "memory");
}
#define CP_COMMIT() asm volatile("cp.async.commit_group;" ::: "memory")
#define CP_WAIT(n)  asm volatile("cp.async.wait_group %0;" :: "n"(n) : "memory")

__device__ __forceinline__ void ldsm4(uint32_t* r, uint32_t addr) {
    asm volatile("ldmatrix.sync.aligned.m8n8.x4.shared.b16 {%0,%1,%2,%3}, [%4];"
                 : "=r"(r[0]), "=r"(r[1]), "=r"(r[2]), "=r"(r[3]) : "r"(addr));
}
__device__ __forceinline__ void mma_bf16(float* c, const uint32_t* a,
                                         uint32_t b0, uint32_t b1) {
    asm volatile(
        "mma.sync.aligned.m16n8k16.row.col.f32.bf16.bf16.f32 "
        "{%0,%1,%2,%3}, {%4,%5,%6,%7}, {%8,%9}, {%0,%1,%2,%3};"
        : "+f"(c[0]), "+f"(c[1]), "+f"(c[2]), "+f"(c[3])
        : "r"(a[0]), "r"(a[1]), "r"(a[2]), "r"(a[3]), "r"(b0), "r"(b1));
}

// ---------------- bf16 3-split ----------------
__device__ __forceinline__ void split3(float x, uint16_t& h, uint16_t& m, uint16_t& l) {
    __nv_bfloat16 bh = __float2bfloat16(x);
    float r = x - __bfloat162float(bh);
    __nv_bfloat16 bm = __float2bfloat16(r);
    float r2 = r - __bfloat162float(bm);
    __nv_bfloat16 bl = __float2bfloat16(r2);
    h = __bfloat16_as_ushort(bh);
    m = __bfloat16_as_ushort(bm);
    l = __bfloat16_as_ushort(bl);
}

// ---------------- prep kernels (warp per row) ----------------
__device__ __forceinline__ void prep_row(const float* __restrict__ src, int row,
                                         __nv_bfloat16 (*dsth)[DDIM],
                                         __nv_bfloat16 (*dstm)[DDIM],
                                         __nv_bfloat16 (*dstl)[DDIM],
                                         float* __restrict__ norm_out) {
    int lane = threadIdx.x & 31;
    const float4* zp = (const float4*)(src + (size_t)row * DDIM) + lane * 2;
    float4 a = zp[0], b = zp[1];
    float v[8] = {a.x, a.y, a.z, a.w, b.x, b.y, b.z, b.w};
    float ns = 0.f;
    uint32_t ph[4], pm[4], pl[4];
    #pragma unroll
    for (int j = 0; j < 4; j++) {
        float x0 = v[2 * j], x1 = v[2 * j + 1];
        ns += x0 * x0 + x1 * x1;
        uint16_t h0, m0, l0, h1, m1, l1;
        split3(x0, h0, m0, l0);
        split3(x1, h1, m1, l1);
        ph[j] = (uint32_t)h1 << 16 | h0;
        pm[j] = (uint32_t)m1 << 16 | m0;
        pl[j] = (uint32_t)l1 << 16 | l0;
    }
    ((uint4*)dsth[row])[lane] = make_uint4(ph[0], ph[1], ph[2], ph[3]);
    ((uint4*)dstm[row])[lane] = make_uint4(pm[0], pm[1], pm[2], pm[3]);
    ((uint4*)dstl[row])[lane] = make_uint4(pl[0], pl[1], pl[2], pl[3]);
    #pragma unroll
    for (int o = 16; o > 0; o >>= 1) ns += __shfl_down_sync(0xffffffffu, ns, o);
    if (lane == 0) *norm_out = ns;
}

__global__ void prep_z(const float* __restrict__ z) {
    int row = blockIdx.x * 8 + (threadIdx.x >> 5);
    prep_row(z, row, g_zspl[0], g_zspl[1], g_zspl[2], &g_znorm[row]);
}
__global__ void prep_cb(const float* __restrict__ cb) {
    int row = blockIdx.x * 8 + (threadIdx.x >> 5);
    prep_row(cb, row, g_cbspl[0], g_cbspl[1], g_cbspl[2], &g_cnorm[row]);
    if (row == 0 && (threadIdx.x & 31) == 0) g_loss = 0.0;
}

// ---------------- stage loader ----------------
__device__ __forceinline__ void load_stage(uint32_t sb, int s, int chunk, int kd,
                                           int rowBase, int tid) {
    const uint32_t zsB = sb + OFF_ZS + s * STAGE_B;
    const uint32_t csB = sb + OFF_CS + s * STAGE_B;
    const int dOff = kd * KD;
    #pragma unroll
    for (int j = 0; j < 12; j++) {
        int q = j * 256 + tid;             // 0..3071
        int sp = q >> 10, rem = q & 1023;
        int r = rem >> 3, c = rem & 7;
        cp_async16(zsB + sp * SPLIT_B + r * 128 + (((c ^ (r & 7))) << 4),
                   &g_zspl[sp][rowBase + r][dOff + c * 8]);
    }
    const int codeBase = chunk * BNC;
    #pragma unroll
    for (int j = 0; j < 12; j++) {
        int q = j * 256 + tid;
        int sp = q >> 10, rem = q & 1023;
        int r = rem >> 3, c = rem & 7;
        cp_async16(csB + sp * SPLIT_B + r * 128 + (((c ^ (r & 7))) << 4),
                   &g_cbspl[sp][codeBase + r][dOff + c * 8]);
    }
}

// ---------------- main HMMA VQ kernel ----------------
__global__ __launch_bounds__(256, 1)
void vq_mma(const float* __restrict__ cb,
            float* __restrict__ zq_out,
            float* __restrict__ ids_out) {
    extern __shared__ char smem[];
    const uint32_t sb = smem_u32(smem);
    const int tid = threadIdx.x;
    const int wid = tid >> 5;
    const uint32_t lane = tid & 31;
    const int mW = wid & 1;        // 2-way M split (64 rows each)
    const int nW = wid >> 1;       // 4-way N split (32 codes each)
    const int rowBase = blockIdx.x * BM;

    float* sCn   = (float*)(smem + OFF_CN);
    float* sRedV = (float*)(smem + OFF_REDV);
    int*   sRedI = (int*)(smem + OFF_REDI);
    int*   sIds  = (int*)(smem + OFF_IDS);
    float* sLoss = (float*)(smem + OFF_LOSS);

    // preload codebook norms
    #pragma unroll
    for (int k = tid; k < KCODES; k += 256) sCn[k] = g_cnorm[k];

    // per-thread ldmatrix address components
    const uint32_t rowAoff = ((uint32_t)(mW * 64) + (lane & 15)) * 128;
    const uint32_t nRowoff = ((uint32_t)(nW * 32) + (lane & 7) + ((lane >> 4) << 3)) * 128;
    const uint32_t swz = lane & 7;
    const uint32_t kHA = lane >> 4;
    const uint32_t kHB = (lane >> 3) & 1;

    const int SA[NTERMS] = {0, 0, 1, 0, 2, 1};
    const int SB[NTERMS] = {0, 1, 0, 2, 0, 1};

    float acc[4][4][4];
    #pragma unroll
    for (int mt = 0; mt < 4; mt++)
        #pragma unroll
        for (int nt = 0; nt < 4; nt++)
            #pragma unroll
            for (int e = 0; e < 4; e++) acc[mt][nt][e] = 0.f;

    float minv[8];
    int   mini[8];
    #pragma unroll
    for (int q = 0; q < 8; q++) { minv[q] = 3.4e38f; mini[q] = 0; }

    // prologue
    load_stage(sb, 0, 0, 0, rowBase, tid);
    CP_COMMIT();

    #pragma unroll 1
    for (int it = 0; it < NIT; it++) {
        if (it + 1 < NIT) {
            load_stage(sb, (it + 1) & 1, (it + 1) >> 2, (it + 1) & 3, rowBase, tid);
            CP_COMMIT();
            CP_WAIT(1);
        } else {
            CP_WAIT(0);
        }
        __syncthreads();

        const int s = it & 1;
        const uint32_t zsB = sb + OFF_ZS + s * STAGE_B;
        const uint32_t csB = sb + OFF_CS + s * STAGE_B;

        #pragma unroll
        for (int t = 0; t < NTERMS; t++) {
            const uint32_t aB = zsB + SA[t] * SPLIT_B + rowAoff;
            const uint32_t bB = csB + SB[t] * SPLIT_B + nRowoff;
            #pragma unroll
            for (int kk = 0; kk < 4; kk++) {
                const uint32_t aCol = ((2u * kk + kHA) ^ swz) << 4;
                const uint32_t bCol = ((2u * kk + kHB) ^ swz) << 4;
                uint32_t a[4][4], b[2][4];
                ldsm4(a[0], aB + 0 * 2048 + aCol);
                ldsm4(a[1], aB + 1 * 2048 + aCol);
                ldsm4(a[2], aB + 2 * 2048 + aCol);
                ldsm4(a[3], aB + 3 * 2048 + aCol);
                ldsm4(b[0], bB + 0 * 2048 + bCol);
                ldsm4(b[1], bB + 1 * 2048 + bCol);
                #pragma unroll
                for (int mt = 0; mt < 4; mt++) {
                    mma_bf16(acc[mt][0], a[mt], b[0][0], b[0][1]);
                    mma_bf16(acc[mt][1], a[mt], b[0][2], b[0][3]);
                    mma_bf16(acc[mt][2], a[mt], b[1][0], b[1][1]);
                    mma_bf16(acc[mt][3], a[mt], b[1][2], b[1][3]);
                }
            }
        }

        if ((it & 3) == 3) {
            // chunk epilogue: e = ||c||^2 - 2 z.c, running argmin (ascending j)
            const int chunk = it >> 2;
            const int jBase = chunk * BNC + nW * 32 + (int)(lane & 3) * 2;
            #pragma unroll
            for (int nt = 0; nt < 4; nt++) {
                const int j0 = jBase + nt * 8;
                const float2 cn = *(const float2*)(sCn + j0);
                #pragma unroll
                for (int mt = 0; mt < 4; mt++) {
                    float e00 = fmaf(-2.f, acc[mt][nt][0], cn.x);
                    float e01 = fmaf(-2.f, acc[mt][nt][1], cn.y);
                    float e10 = fmaf(-2.f, acc[mt][nt][2], cn.x);
                    float e11 = fmaf(-2.f, acc[mt][nt][3], cn.y);
                    if (e00 < minv[2 * mt])     { minv[2 * mt] = e00;     mini[2 * mt] = j0; }
                    if (e01 < minv[2 * mt])     { minv[2 * mt] = e01;     mini[2 * mt] = j0 + 1; }
                    if (e10 < minv[2 * mt + 1]) { minv[2 * mt + 1] = e10; mini[2 * mt + 1] = j0; }
                    if (e11 < minv[2 * mt + 1]) { minv[2 * mt + 1] = e11; mini[2 * mt + 1] = j0 + 1; }
                    acc[mt][nt][0] = 0.f; acc[mt][nt][1] = 0.f;
                    acc[mt][nt][2] = 0.f; acc[mt][nt][3] = 0.f;
                }
            }
        }
        __syncthreads();
    }

    // ---- cross-lane reduction (4 lanes share each row within warp) ----
    #pragma unroll
    for (int q = 0; q < 8; q++) {
        float v = minv[q];
        int   id = mini[q];
        #pragma unroll
        for (int off = 1; off <= 2; off <<= 1) {
            float vo = __shfl_xor_sync(0xffffffffu, v, off);
            int   io = __shfl_xor_sync(0xffffffffu, id, off);
            if (vo < v || (vo == v && io < id)) { v = vo; id = io; }
        }
        if ((lane & 3) == 0) {
            const int mt = q >> 1, h = q & 1;
            const int r = mW * 64 + mt * 16 + (int)(lane >> 2) + h * 8;
            sRedV[r * 4 + nW] = v;
            sRedI[r * 4 + nW] = id;
        }
    }
    __syncthreads();

    // ---- per-row final (threads 0..127) ----
    if (tid < BM) {
        float bv = sRedV[tid * 4];
        int   bj = sRedI[tid * 4];
        #pragma unroll
        for (int w = 1; w < 4; w++) {
            float v = sRedV[tid * 4 + w];
            int   j = sRedI[tid * 4 + w];
            if (v < bv || (v == bv && j < bj)) { bv = v; bj = j; }
        }
        sIds[tid] = bj;
        ids_out[rowBase + tid] = (float)bj;
        float lv = bv + g_znorm[rowBase + tid];   // ||z - c*||^2
        #pragma unroll
        for (int o = 16; o > 0; o >>= 1) lv += __shfl_down_sync(0xffffffffu, lv, o);
        if ((tid & 31) == 0) sLoss[tid >> 5] = lv;
    }
    __syncthreads();

    if (tid == 0)
        atomicAdd(&g_loss, (double)(sLoss[0] + sLoss[1] + sLoss[2] + sLoss[3]));

    // ---- gather z_q = codebook[id] ----
    for (int rr = wid; rr < BM; rr += 8) {
        const int id = sIds[rr];
        const float4* src = (const float4*)(cb + (size_t)id * DDIM);
        float4* dst = (float4*)(zq_out + (size_t)(rowBase + rr) * DDIM);
        dst[lane]      = src[lane];
        dst[lane + 32] = src[lane + 32];
    }
}

// ---------------- loss finalize ----------------
__global__ void finalize_kernel(float* __restrict__ loss_out) {
    *loss_out = (float)(g_loss * (1.0 + QTZ_BETA) / ((double)NROWS * (double)DDIM));
}

// ---------------- launch ----------------
extern "C" void kernel_launch(void* const* d_in, const int* in_sizes, int n_in,
                              void* d_out, int out_size) {
    const float* z  = (const float*)d_in[0];
    const float* cb = (const float*)d_in[1];
    float* out = (float*)d_out;

    float* zq_out   = out;                          // N*D
    float* loss_out = out + (size_t)NROWS * DDIM;   // 1
    float* ids_out  = loss_out + 1;                 // N

    cudaFuncSetAttribute(vq_mma, cudaFuncAttributeMaxDynamicSharedMemorySize, SMEM_TOTAL);

    prep_z<<<NROWS / 8, 256>>>(z);
    prep_cb<<<KCODES / 8, 256>>>(cb);
    vq_mma<<<NROWS / BM, 256, SMEM_TOTAL>>>(cb, zq_out, ids_out);
    finalize_kernel<<<1, 1>>>(loss_out);
}

// round 4
// speedup vs baseline: 4.2401x; 3.4869x over previous
#include <cuda_runtime.h>
#include <cuda_bf16.h>
#include <cstdint>

#define NROWS  65536
#define DDIM   256
#define KCODES 4096
#define QTZ_BETA 0.25
#define BM 128
#define BNC 128                 // codes per chunk
#define NCHUNK (KCODES / BNC)   // 32
#define KD 128                  // d per stage
#define NIT (NCHUNK * 2)        // 64
#define CAP 48

// -------- device scratch --------
__device__ __nv_bfloat16 g_zh[NROWS][DDIM];    // 32MB
__device__ __nv_bfloat16 g_cbh[KCODES][DDIM];  // 2MB
__device__ float  g_znorm[NROWS];
__device__ float  g_cnorm[KCODES];
__device__ float  g_maxcn;
__device__ double g_loss;
__device__ int    g_ccount[NROWS];
__device__ int    g_cand[NROWS][CAP];

// -------- smem map (bytes) --------
#define STG 32768
#define OFF_Z    0                    // 2 x 32KB
#define OFF_C    (2 * STG)            // 2 x 32KB
#define OFF_CN   (4 * STG)            // 16KB
#define OFF_MIN  (OFF_CN + 16384)     // 512
#define OFF_CNT  (OFF_MIN + 512)      // 512
#define OFF_MR   (OFF_CNT + 512)      // 512
#define OFF_CAND (OFF_MR + 512)       // 128*48*4 = 24576
#define SMEM_TOTAL (OFF_CAND + 24576) // 173568

// ---------------- PTX helpers ----------------
__device__ __forceinline__ uint32_t smem_u32(const void* p) {
    uint32_t a;
    asm("{ .reg .u64 t; cvta.to.shared.u64 t, %1; cvt.u32.u64 %0, t; }" : "=r"(a) : "l"(p));
    return a;
}
__device__ __forceinline__ void cp_async16(uint32_t dst, const void* src) {
    asm volatile("cp.async.cg.shared.global [%0], [%1], 16;" :: "r"(dst), "l"(src) : "memory");
}
#define CP_COMMIT() asm volatile("cp.async.commit_group;" ::: "memory")
#define CP_WAIT(n)  asm volatile("cp.async.wait_group %0;" :: "n"(n) : "memory")

__device__ __forceinline__ void ldsm4(uint32_t* r, uint32_t addr) {
    asm volatile("ldmatrix.sync.aligned.m8n8.x4.shared.b16 {%0,%1,%2,%3}, [%4];"
                 : "=r"(r[0]), "=r"(r[1]), "=r"(r[2]), "=r"(r[3]) : "r"(addr));
}
__device__ __forceinline__ void mma_bf16(float* c, const uint32_t* a,
                                         uint32_t b0, uint32_t b1) {
    asm volatile(
        "mma.sync.aligned.m16n8k16.row.col.f32.bf16.bf16.f32 "
        "{%0,%1,%2,%3}, {%4,%5,%6,%7}, {%8,%9}, {%0,%1,%2,%3};"
        : "+f"(c[0]), "+f"(c[1]), "+f"(c[2]), "+f"(c[3])
        : "r"(a[0]), "r"(a[1]), "r"(a[2]), "r"(a[3]), "r"(b0), "r"(b1));
}

// ordered-uint keys for float atomicMin
__device__ __forceinline__ uint32_t fkey(float f) {
    uint32_t u = __float_as_uint(f);
    return (u & 0x80000000u) ? ~u : (u | 0x80000000u);
}
__device__ __forceinline__ float funkey(uint32_t k) {
    return __uint_as_float((k & 0x80000000u) ? (k & 0x7fffffffu) : ~k);
}

// ---------------- init ----------------
__global__ void init_kernel() { g_loss = 0.0; g_maxcn = 0.f; }

// ---------------- prep: bf16 round + norms ----------------
__device__ __forceinline__ float prep_row(const float* __restrict__ src, int row,
                                          __nv_bfloat16 (*dst)[DDIM]) {
    int lane = threadIdx.x & 31;
    const float4* zp = (const float4*)(src + (size_t)row * DDIM) + lane * 2;
    float4 a = zp[0], b = zp[1];
    float v[8] = {a.x, a.y, a.z, a.w, b.x, b.y, b.z, b.w};
    float ns = 0.f;
    uint32_t p[4];
    #pragma unroll
    for (int j = 0; j < 4; j++) {
        float x0 = v[2 * j], x1 = v[2 * j + 1];
        ns += x0 * x0 + x1 * x1;
        __nv_bfloat162 h2 = __float22bfloat162_rn(make_float2(x0, x1));
        p[j] = *reinterpret_cast<uint32_t*>(&h2);
    }
    ((uint4*)dst[row])[lane] = make_uint4(p[0], p[1], p[2], p[3]);
    #pragma unroll
    for (int o = 16; o > 0; o >>= 1) ns += __shfl_down_sync(0xffffffffu, ns, o);
    return ns;
}
__global__ void prep_z(const float* __restrict__ z) {
    int row = blockIdx.x * 8 + (threadIdx.x >> 5);
    float ns = prep_row(z, row, g_zh);
    if ((threadIdx.x & 31) == 0) g_znorm[row] = ns;
}
__global__ void prep_cb(const float* __restrict__ cb) {
    int row = blockIdx.x * 8 + (threadIdx.x >> 5);
    float ns = prep_row(cb, row, g_cbh);
    if ((threadIdx.x & 31) == 0) {
        g_cnorm[row] = ns;
        atomicMax((int*)&g_maxcn, __float_as_int(ns));
    }
}

// ---------------- pass1 stage loader ----------------
__device__ __forceinline__ void load_stage(uint32_t sb, int it, int rowBase, int tid) {
    const int s = it & 1;
    const int chunk = it >> 1;
    const int dOff = (it & 1) * KD;
    const uint32_t zB = sb + OFF_Z + s * STG;
    const uint32_t cB = sb + OFF_C + s * STG;
    #pragma unroll
    for (int j = 0; j < 8; j++) {
        int q = j * 256 + tid;          // 0..2047
        int r = q >> 4, c = q & 15;
        cp_async16(zB + r * 256 + (((c ^ (r & 7))) << 4),
                   &g_zh[rowBase + r][dOff + c * 8]);
    }
    const int codeBase = chunk * BNC;
    #pragma unroll
    for (int j = 0; j < 8; j++) {
        int q = j * 256 + tid;
        int r = q >> 4, c = q & 15;
        cp_async16(cB + r * 256 + (((c ^ (r & 7))) << 4),
                   &g_cbh[codeBase + r][dOff + c * 8]);
    }
}

// ---------------- pass1: approx GEMM + candidate collection ----------------
__global__ __launch_bounds__(256, 1)
void vq_approx() {
    extern __shared__ char smem[];
    const uint32_t sb = smem_u32(smem);
    const int tid = threadIdx.x;
    const uint32_t lane = tid & 31;
    const int wid = tid >> 5;
    const int mW = wid & 1;
    const int nW = wid >> 1;
    const int rowBase = blockIdx.x * BM;

    float*    sCn   = (float*)(smem + OFF_CN);
    uint32_t* sMin  = (uint32_t*)(smem + OFF_MIN);
    int*      sCnt  = (int*)(smem + OFF_CNT);
    float*    sMr   = (float*)(smem + OFF_MR);
    int*      sCand = (int*)(smem + OFF_CAND);

    #pragma unroll
    for (int k = tid; k < KCODES; k += 256) sCn[k] = g_cnorm[k];
    if (tid < BM) {
        sMin[tid] = 0xFFFFFFFFu;
        sCnt[tid] = 0;
        sMr[tid]  = 0.034f * sqrtf(g_znorm[rowBase + tid]) * sqrtf(g_maxcn) + 0.25f;
    }

    const uint32_t rowAoff = ((uint32_t)(mW * 64) + (lane & 15)) * 256;
    const uint32_t nRowoff = ((uint32_t)(nW * 32) + (lane & 7) + ((lane >> 4) << 3)) * 256;
    const uint32_t swz = lane & 7;
    const uint32_t kHA = lane >> 4;
    const uint32_t kHB = (lane >> 3) & 1;

    float acc[4][4][4];
    #pragma unroll
    for (int mt = 0; mt < 4; mt++)
        #pragma unroll
        for (int nt = 0; nt < 4; nt++)
            #pragma unroll
            for (int e = 0; e < 4; e++) acc[mt][nt][e] = 0.f;

    load_stage(sb, 0, rowBase, tid);
    CP_COMMIT();

    #pragma unroll 1
    for (int it = 0; it < NIT; it++) {
        if (it + 1 < NIT) {
            load_stage(sb, it + 1, rowBase, tid);
            CP_COMMIT();
            CP_WAIT(1);
        } else {
            CP_WAIT(0);
        }
        __syncthreads();

        const int s = it & 1;
        const uint32_t aB = sb + OFF_Z + s * STG + rowAoff;
        const uint32_t bB = sb + OFF_C + s * STG + nRowoff;

        #pragma unroll
        for (int kk = 0; kk < 8; kk++) {
            const uint32_t aCol = ((2u * kk + kHA) ^ swz) << 4;
            const uint32_t bCol = ((2u * kk + kHB) ^ swz) << 4;
            uint32_t a[4][4], b[2][4];
            ldsm4(a[0], aB + 0 * 4096 + aCol);
            ldsm4(a[1], aB + 1 * 4096 + aCol);
            ldsm4(a[2], aB + 2 * 4096 + aCol);
            ldsm4(a[3], aB + 3 * 4096 + aCol);
            ldsm4(b[0], bB + 0 * 4096 + bCol);
            ldsm4(b[1], bB + 1 * 4096 + bCol);
            #pragma unroll
            for (int mt = 0; mt < 4; mt++) {
                mma_bf16(acc[mt][0], a[mt], b[0][0], b[0][1]);
                mma_bf16(acc[mt][1], a[mt], b[0][2], b[0][3]);
                mma_bf16(acc[mt][2], a[mt], b[1][0], b[1][1]);
                mma_bf16(acc[mt][3], a[mt], b[1][2], b[1][3]);
            }
        }

        if (it & 1) {
            const int chunk = it >> 1;
            const int jb = chunk * BNC + nW * 32 + (int)(lane & 3) * 2;

            // e = cn - 2 dot ; per-row local min -> shared atomicMin
            float rmin[8];
            #pragma unroll
            for (int q = 0; q < 8; q++) rmin[q] = 3.4e38f;
            #pragma unroll
            for (int nt = 0; nt < 4; nt++) {
                const float2 cn = *(const float2*)(sCn + jb + nt * 8);
                #pragma unroll
                for (int mt = 0; mt < 4; mt++) {
                    float e0 = fmaf(-2.f, acc[mt][nt][0], cn.x);
                    float e1 = fmaf(-2.f, acc[mt][nt][1], cn.y);
                    float e2 = fmaf(-2.f, acc[mt][nt][2], cn.x);
                    float e3 = fmaf(-2.f, acc[mt][nt][3], cn.y);
                    acc[mt][nt][0] = e0; acc[mt][nt][1] = e1;
                    acc[mt][nt][2] = e2; acc[mt][nt][3] = e3;
                    rmin[2 * mt]     = fminf(rmin[2 * mt],     fminf(e0, e1));
                    rmin[2 * mt + 1] = fminf(rmin[2 * mt + 1], fminf(e2, e3));
                }
            }
            #pragma unroll
            for (int mt = 0; mt < 4; mt++)
                #pragma unroll
                for (int h = 0; h < 2; h++) {
                    int r = mW * 64 + mt * 16 + (int)(lane >> 2) + h * 8;
                    atomicMin(&sMin[r], fkey(rmin[2 * mt + h]));
                }
            __syncthreads();

            // insert candidates within margin of shared min
            #pragma unroll
            for (int mt = 0; mt < 4; mt++)
                #pragma unroll
                for (int h = 0; h < 2; h++) {
                    int r = mW * 64 + mt * 16 + (int)(lane >> 2) + h * 8;
                    float th = funkey(sMin[r]) + sMr[r];
                    #pragma unroll
                    for (int nt = 0; nt < 4; nt++) {
                        float ev0 = acc[mt][nt][2 * h];
                        float ev1 = acc[mt][nt][2 * h + 1];
                        if (ev0 <= th) {
                            int p = atomicAdd(&sCnt[r], 1);
                            if (p < CAP) sCand[r * CAP + p] = jb + nt * 8;
                        }
                        if (ev1 <= th) {
                            int p = atomicAdd(&sCnt[r], 1);
                            if (p < CAP) sCand[r * CAP + p] = jb + nt * 8 + 1;
                        }
                    }
                }
            // reset accumulators for next chunk
            #pragma unroll
            for (int mt = 0; mt < 4; mt++)
                #pragma unroll
                for (int nt = 0; nt < 4; nt++) {
                    acc[mt][nt][0] = 0.f; acc[mt][nt][1] = 0.f;
                    acc[mt][nt][2] = 0.f; acc[mt][nt][3] = 0.f;
                }
        }
        __syncthreads();
    }

    // flush candidate lists to global
    if (tid < BM) {
        const int cnt = sCnt[tid];
        g_ccount[rowBase + tid] = cnt;
        const int m = cnt < CAP ? cnt : CAP;
        for (int i = 0; i < m; i++)
            g_cand[rowBase + tid][i] = sCand[tid * CAP + i];
    }
}

// ---------------- pass2: exact fp32 rescore + outputs ----------------
__device__ __forceinline__ float cand_d2(const float4& za, const float4& zb,
                                         const float* __restrict__ cb, int id,
                                         float zn, int lane) {
    const float4* cp = (const float4*)(cb + (size_t)id * DDIM);
    float4 ca = cp[lane * 2], cc = cp[lane * 2 + 1];
    float d = za.x * ca.x;
    d = fmaf(za.y, ca.y, d); d = fmaf(za.z, ca.z, d); d = fmaf(za.w, ca.w, d);
    d = fmaf(zb.x, cc.x, d); d = fmaf(zb.y, cc.y, d);
    d = fmaf(zb.z, cc.z, d); d = fmaf(zb.w, cc.w, d);
    #pragma unroll
    for (int o = 16; o > 0; o >>= 1) d += __shfl_xor_sync(0xffffffffu, d, o);
    return zn - 2.f * d + g_cnorm[id];
}

__global__ __launch_bounds__(256, 1)
void vq_rescore(const float* __restrict__ z, const float* __restrict__ cb,
                float* __restrict__ zq, float* __restrict__ ids_out) {
    __shared__ float sL[8];
    const int w = threadIdx.x >> 5, lane = threadIdx.x & 31;
    const int row = blockIdx.x * 8 + w;

    const float4* zp = (const float4*)(z + (size_t)row * DDIM);
    const float4 za = zp[lane * 2], zb = zp[lane * 2 + 1];
    const float zn = g_znorm[row];
    const int n = g_ccount[row];

    float best = 3.4e38f;
    int bid = 0x7fffffff;
    if (n <= CAP) {
        for (int i = 0; i < n; i++) {
            const int id = g_cand[row][i];
            float d2 = cand_d2(za, zb, cb, id, zn, lane);
            if (d2 < best || (d2 == best && id < bid)) { best = d2; bid = id; }
        }
    } else {
        for (int id = 0; id < KCODES; id++) {
            float d2 = cand_d2(za, zb, cb, id, zn, lane);
            if (d2 < best || (d2 == best && id < bid)) { best = d2; bid = id; }
        }
    }

    ids_out[row] = (float)bid;
    const float4* cp = (const float4*)(cb + (size_t)bid * DDIM);
    float4* dst = (float4*)(zq + (size_t)row * DDIM);
    dst[lane * 2]     = cp[lane * 2];
    dst[lane * 2 + 1] = cp[lane * 2 + 1];

    if (lane == 0) sL[w] = best;
    __syncthreads();
    if (threadIdx.x == 0) {
        float s = 0.f;
        #pragma unroll
        for (int i = 0; i < 8; i++) s += sL[i];
        atomicAdd(&g_loss, (double)s);
    }
}

// ---------------- loss finalize ----------------
__global__ void finalize_kernel(float* __restrict__ loss_out) {
    *loss_out = (float)(g_loss * (1.0 + QTZ_BETA) / ((double)NROWS * (double)DDIM));
}

// ---------------- launch ----------------
extern "C" void kernel_launch(void* const* d_in, const int* in_sizes, int n_in,
                              void* d_out, int out_size) {
    const float* z  = (const float*)d_in[0];
    const float* cb = (const float*)d_in[1];
    float* out = (float*)d_out;

    float* zq_out   = out;                          // N*D
    float* loss_out = out + (size_t)NROWS * DDIM;   // 1
    float* ids_out  = loss_out + 1;                 // N

    cudaFuncSetAttribute(vq_approx, cudaFuncAttributeMaxDynamicSharedMemorySize, SMEM_TOTAL);

    init_kernel<<<1, 1>>>();
    prep_z<<<NROWS / 8, 256>>>(z);
    prep_cb<<<KCODES / 8, 256>>>(cb);
    vq_approx<<<NROWS / BM, 256, SMEM_TOTAL>>>();
    vq_rescore<<<NROWS / 8, 256>>>(z, cb, zq_out, ids_out);
    finalize_kernel<<<1, 1>>>(loss_out);
}

// round 6
// speedup vs baseline: 4.3749x; 1.0318x over previous
#include <cuda_runtime.h>
#include <cuda_bf16.h>
#include <cstdint>

#define NROWS  65536
#define DDIM   256
#define KCODES 4096
#define QTZ_BETA 0.25
#define BM 128
#define BNC 128                 // codes per chunk
#define NCHUNK (KCODES / BNC)   // 32
#define KD 128                  // d per stage
#define NIT (NCHUNK * 2)        // 64
#define CAP 64

// -------- device scratch --------
__device__ __nv_bfloat16 g_zh[NROWS][DDIM];    // 32MB
__device__ __nv_bfloat16 g_cbh[KCODES][DDIM];  // 2MB
__device__ float  g_znorm[NROWS];
__device__ float  g_cnorm[KCODES];
__device__ float  g_maxcn;
__device__ double g_loss;
__device__ int    g_ccount[NROWS];
__device__ int    g_cand[NROWS][CAP];

// -------- smem map (bytes) --------
// 3 stages of [z(32KB) | c(32KB)], then min/cnt/margin/cand
#define STGP 65536
#define OFF_MIN  (3 * STGP)             // 196608 (128 u32)
#define OFF_CNT  (OFF_MIN + 512)
#define OFF_MR   (OFF_CNT + 512)
#define OFF_CAND (OFF_MR + 512)         // 198144: 128*64*4 = 32768
#define SMEM_TOTAL (OFF_CAND + 32768)   // 230912

// ---------------- PTX helpers ----------------
__device__ __forceinline__ uint32_t smem_u32(const void* p) {
    uint32_t a;
    asm("{ .reg .u64 t; cvta.to.shared.u64 t, %1; cvt.u32.u64 %0, t; }" : "=r"(a) : "l"(p));
    return a;
}
__device__ __forceinline__ void cp_async16(uint32_t dst, const void* src) {
    asm volatile("cp.async.cg.shared.global [%0], [%1], 16;" :: "r"(dst), "l"(src) : "memory");
}
#define CP_COMMIT() asm volatile("cp.async.commit_group;" ::: "memory")
#define CP_WAIT(n)  asm volatile("cp.async.wait_group %0;" :: "n"(n) : "memory")

__device__ __forceinline__ void ldsm4(uint32_t* r, uint32_t addr) {
    asm volatile("ldmatrix.sync.aligned.m8n8.x4.shared.b16 {%0,%1,%2,%3}, [%4];"
                 : "=r"(r[0]), "=r"(r[1]), "=r"(r[2]), "=r"(r[3]) : "r"(addr));
}
__device__ __forceinline__ void mma_bf16(float* c, const uint32_t* a,
                                         uint32_t b0, uint32_t b1) {
    asm volatile(
        "mma.sync.aligned.m16n8k16.row.col.f32.bf16.bf16.f32 "
        "{%0,%1,%2,%3}, {%4,%5,%6,%7}, {%8,%9}, {%0,%1,%2,%3};"
        : "+f"(c[0]), "+f"(c[1]), "+f"(c[2]), "+f"(c[3])
        : "r"(a[0]), "r"(a[1]), "r"(a[2]), "r"(a[3]), "r"(b0), "r"(b1));
}

// ordered-uint keys for float atomicMin
__device__ __forceinline__ uint32_t fkey(float f) {
    uint32_t u = __float_as_uint(f);
    return (u & 0x80000000u) ? ~u : (u | 0x80000000u);
}
__device__ __forceinline__ float funkey(uint32_t k) {
    return __uint_as_float((k & 0x80000000u) ? (k & 0x7fffffffu) : ~k);
}

// ---------------- init ----------------
__global__ void init_kernel() { g_loss = 0.0; g_maxcn = 0.f; }

// ---------------- prep: bf16 round + norms ----------------
__device__ __forceinline__ float prep_row(const float* __restrict__ src, int row,
                                          __nv_bfloat16 (*dst)[DDIM]) {
    int lane = threadIdx.x & 31;
    const float4* zp = (const float4*)(src + (size_t)row * DDIM) + lane * 2;
    float4 a = zp[0], b = zp[1];
    float v[8] = {a.x, a.y, a.z, a.w, b.x, b.y, b.z, b.w};
    float ns = 0.f;
    uint32_t p[4];
    #pragma unroll
    for (int j = 0; j < 4; j++) {
        float x0 = v[2 * j], x1 = v[2 * j + 1];
        ns += x0 * x0 + x1 * x1;
        __nv_bfloat162 h2 = __float22bfloat162_rn(make_float2(x0, x1));
        p[j] = *reinterpret_cast<uint32_t*>(&h2);
    }
    ((uint4*)dst[row])[lane] = make_uint4(p[0], p[1], p[2], p[3]);
    #pragma unroll
    for (int o = 16; o > 0; o >>= 1) ns += __shfl_down_sync(0xffffffffu, ns, o);
    return ns;
}
__global__ void prep_z(const float* __restrict__ z) {
    int row = blockIdx.x * 8 + (threadIdx.x >> 5);
    float ns = prep_row(z, row, g_zh);
    if ((threadIdx.x & 31) == 0) g_znorm[row] = ns;
}
__global__ void prep_cb(const float* __restrict__ cb) {
    int row = blockIdx.x * 8 + (threadIdx.x >> 5);
    float ns = prep_row(cb, row, g_cbh);
    if ((threadIdx.x & 31) == 0) {
        g_cnorm[row] = ns;
        atomicMax((int*)&g_maxcn, __float_as_int(ns));
    }
}

// ---------------- pass1 stage loader (512 threads) ----------------
__device__ __forceinline__ void load_stage(uint32_t sb, int it, int rowBase, int tid) {
    const uint32_t stg = sb + (uint32_t)(it % 3) * STGP;
    const int dOff = (it & 1) * KD;
    const int chunk = it >> 1;
    #pragma unroll
    for (int j = 0; j < 4; j++) {
        int q = j * 512 + tid;          // 0..2047
        int r = q >> 4, c = q & 15;
        cp_async16(stg + r * 256 + (((c ^ (r & 7))) << 4),
                   &g_zh[rowBase + r][dOff + c * 8]);
    }
    const int codeBase = chunk * BNC;
    #pragma unroll
    for (int j = 0; j < 4; j++) {
        int q = j * 512 + tid;
        int r = q >> 4, c = q & 15;
        cp_async16(stg + 32768 + r * 256 + (((c ^ (r & 7))) << 4),
                   &g_cbh[codeBase + r][dOff + c * 8]);
    }
}

// ---------------- pass1: approx GEMM + candidate collection ----------------
__global__ __launch_bounds__(512, 1)
void vq_approx() {
    extern __shared__ char smem[];
    const uint32_t sb = smem_u32(smem);
    const int tid = threadIdx.x;
    const uint32_t lane = tid & 31;
    const int wid = tid >> 5;
    const int mW = wid & 3;        // 4-way M split (32 rows each)
    const int nW = wid >> 2;       // 4-way N split (32 codes each)
    const int rowBase = blockIdx.x * BM;

    uint32_t* sMin  = (uint32_t*)(smem + OFF_MIN);
    int*      sCnt  = (int*)(smem + OFF_CNT);
    float*    sMr   = (float*)(smem + OFF_MR);
    int*      sCand = (int*)(smem + OFF_CAND);

    if (tid < BM) {
        sMin[tid] = 0xFFFFFFFFu;
        sCnt[tid] = 0;
        sMr[tid]  = 0.034f * sqrtf(g_znorm[rowBase + tid]) * sqrtf(g_maxcn) + 0.25f;
    }

    const uint32_t rowAoff = ((uint32_t)(mW * 32) + (lane & 15)) * 256;
    const uint32_t nRowoff = ((uint32_t)(nW * 32) + (lane & 7) + ((lane >> 4) << 3)) * 256;
    const uint32_t swz = lane & 7;
    const uint32_t kHA = lane >> 4;
    const uint32_t kHB = (lane >> 3) & 1;

    float acc[2][4][4];
    #pragma unroll
    for (int mt = 0; mt < 2; mt++)
        #pragma unroll
        for (int nt = 0; nt < 4; nt++)
            #pragma unroll
            for (int e = 0; e < 4; e++) acc[mt][nt][e] = 0.f;

    load_stage(sb, 0, rowBase, tid);
    CP_COMMIT();
    load_stage(sb, 1, rowBase, tid);
    CP_COMMIT();

    #pragma unroll 1
    for (int it = 0; it < NIT; it++) {
        // stage it complete for *this* thread's copies...
        CP_WAIT(1);
        // ...and after the barrier, complete+visible for everyone.
        // The same barrier also retires all reads of stage it-1,
        // making its buffer ((it+2)%3) safe to overwrite below.
        __syncthreads();
        if (it + 2 < NIT) load_stage(sb, it + 2, rowBase, tid);
        CP_COMMIT();                   // empty group near the end keeps count aligned

        const uint32_t stg = sb + (uint32_t)(it % 3) * STGP;
        const uint32_t aB = stg + rowAoff;
        const uint32_t bB = stg + 32768 + nRowoff;

        #pragma unroll
        for (int kk = 0; kk < 8; kk++) {
            const uint32_t aCol = ((2u * kk + kHA) ^ swz) << 4;
            const uint32_t bCol = ((2u * kk + kHB) ^ swz) << 4;
            uint32_t a[2][4], b[2][4];
            ldsm4(a[0], aB + 0 * 4096 + aCol);
            ldsm4(a[1], aB + 1 * 4096 + aCol);
            ldsm4(b[0], bB + 0 * 4096 + bCol);
            ldsm4(b[1], bB + 1 * 4096 + bCol);
            #pragma unroll
            for (int mt = 0; mt < 2; mt++) {
                mma_bf16(acc[mt][0], a[mt], b[0][0], b[0][1]);
                mma_bf16(acc[mt][1], a[mt], b[0][2], b[0][3]);
                mma_bf16(acc[mt][2], a[mt], b[1][0], b[1][1]);
                mma_bf16(acc[mt][3], a[mt], b[1][2], b[1][3]);
            }
        }

        if (it & 1) {
            // chunk epilogue: e = ||c||^2 - 2 z.c; stale-min threshold, no barrier
            const int chunk = it >> 1;
            const int jb = chunk * BNC + nW * 32 + (int)(lane & 3) * 2;

            float rmin[4];
            #pragma unroll
            for (int q = 0; q < 4; q++) rmin[q] = 3.4e38f;

            #pragma unroll
            for (int nt = 0; nt < 4; nt++) {
                const float2 cn = __ldg((const float2*)(g_cnorm + jb + nt * 8));
                #pragma unroll
                for (int mt = 0; mt < 2; mt++) {
                    float e0 = fmaf(-2.f, acc[mt][nt][0], cn.x);
                    float e1 = fmaf(-2.f, acc[mt][nt][1], cn.y);
                    float e2 = fmaf(-2.f, acc[mt][nt][2], cn.x);
                    float e3 = fmaf(-2.f, acc[mt][nt][3], cn.y);
                    acc[mt][nt][0] = e0; acc[mt][nt][1] = e1;
                    acc[mt][nt][2] = e2; acc[mt][nt][3] = e3;
                    rmin[2 * mt]     = fminf(rmin[2 * mt],     fminf(e0, e1));
                    rmin[2 * mt + 1] = fminf(rmin[2 * mt + 1], fminf(e2, e3));
                }
            }
            // reduce over the 4 lanes sharing each row (lane&3 group)
            #pragma unroll
            for (int q = 0; q < 4; q++) {
                rmin[q] = fminf(rmin[q], __shfl_xor_sync(0xffffffffu, rmin[q], 1));
                rmin[q] = fminf(rmin[q], __shfl_xor_sync(0xffffffffu, rmin[q], 2));
            }
            #pragma unroll
            for (int q = 0; q < 4; q++) {
                const int mt = q >> 1, h = q & 1;
                const int r = mW * 32 + mt * 16 + (int)(lane >> 2) + h * 8;
                if ((lane & 3) == 0) atomicMin(&sMin[r], fkey(rmin[q]));
                const float gm = funkey(sMin[r]);         // stale-safe
                const float th = fminf(gm, rmin[q]) + sMr[r];
                #pragma unroll
                for (int nt = 0; nt < 4; nt++) {
                    const float ev0 = acc[mt][nt][2 * h];
                    const float ev1 = acc[mt][nt][2 * h + 1];
                    if (ev0 <= th) {
                        int p = atomicAdd(&sCnt[r], 1);
                        if (p < CAP) sCand[r * CAP + p] = jb + nt * 8;
                    }
                    if (ev1 <= th) {
                        int p = atomicAdd(&sCnt[r], 1);
                        if (p < CAP) sCand[r * CAP + p] = jb + nt * 8 + 1;
                    }
                }
            }
            #pragma unroll
            for (int mt = 0; mt < 2; mt++)
                #pragma unroll
                for (int nt = 0; nt < 4; nt++) {
                    acc[mt][nt][0] = 0.f; acc[mt][nt][1] = 0.f;
                    acc[mt][nt][2] = 0.f; acc[mt][nt][3] = 0.f;
                }
        }
    }

    __syncthreads();
    if (tid < BM) {
        const int cnt = sCnt[tid];
        g_ccount[rowBase + tid] = cnt;
        const int m = cnt < CAP ? cnt : CAP;
        for (int i = 0; i < m; i++)
            g_cand[rowBase + tid][i] = sCand[tid * CAP + i];
    }
}

// ---------------- pass2: exact fp32 rescore + outputs ----------------
__device__ __forceinline__ float cand_d2(const float4& za, const float4& zb,
                                         const float* __restrict__ cb, int id,
                                         float zn, int lane) {
    const float4* cp = (const float4*)(cb + (size_t)id * DDIM);
    float4 ca = cp[lane * 2], cc = cp[lane * 2 + 1];
    float d = za.x * ca.x;
    d = fmaf(za.y, ca.y, d); d = fmaf(za.z, ca.z, d); d = fmaf(za.w, ca.w, d);
    d = fmaf(zb.x, cc.x, d); d = fmaf(zb.y, cc.y, d);
    d = fmaf(zb.z, cc.z, d); d = fmaf(zb.w, cc.w, d);
    #pragma unroll
    for (int o = 16; o > 0; o >>= 1) d += __shfl_xor_sync(0xffffffffu, d, o);
    return zn - 2.f * d + g_cnorm[id];
}

__global__ __launch_bounds__(256, 1)
void vq_rescore(const float* __restrict__ z, const float* __restrict__ cb,
                float* __restrict__ zq, float* __restrict__ ids_out) {
    __shared__ float sL[8];
    const int w = threadIdx.x >> 5, lane = threadIdx.x & 31;
    const int row = blockIdx.x * 8 + w;

    const float4* zp = (const float4*)(z + (size_t)row * DDIM);
    const float4 za = zp[lane * 2], zb = zp[lane * 2 + 1];
    const float zn = g_znorm[row];
    const int n = g_ccount[row];

    float best = 3.4e38f;
    int bid = 0x7fffffff;
    if (n <= CAP) {
        for (int i = 0; i < n; i++) {
            const int id = g_cand[row][i];
            float d2 = cand_d2(za, zb, cb, id, zn, lane);
            if (d2 < best || (d2 == best && id < bid)) { best = d2; bid = id; }
        }
    } else {
        for (int id = 0; id < KCODES; id++) {
            float d2 = cand_d2(za, zb, cb, id, zn, lane);
            if (d2 < best || (d2 == best && id < bid)) { best = d2; bid = id; }
        }
    }

    ids_out[row] = (float)bid;
    const float4* cp = (const float4*)(cb + (size_t)bid * DDIM);
    float4* dst = (float4*)(zq + (size_t)row * DDIM);
    dst[lane * 2]     = cp[lane * 2];
    dst[lane * 2 + 1] = cp[lane * 2 + 1];

    if (lane == 0) sL[w] = best;
    __syncthreads();
    if (threadIdx.x == 0) {
        float s = 0.f;
        #pragma unroll
        for (int i = 0; i < 8; i++) s += sL[i];
        atomicAdd(&g_loss, (double)s);
    }
}

// ---------------- loss finalize ----------------
__global__ void finalize_kernel(float* __restrict__ loss_out) {
    *loss_out = (float)(g_loss * (1.0 + QTZ_BETA) / ((double)NROWS * (double)DDIM));
}

// ---------------- launch ----------------
extern "C" void kernel_launch(void* const* d_in, const int* in_sizes, int n_in,
                              void* d_out, int out_size) {
    const float* z  = (const float*)d_in[0];
    const float* cb = (const float*)d_in[1];
    float* out = (float*)d_out;

    float* zq_out   = out;                          // N*D
    float* loss_out = out + (size_t)NROWS * DDIM;   // 1
    float* ids_out  = loss_out + 1;                 // N

    cudaFuncSetAttribute(vq_approx, cudaFuncAttributeMaxDynamicSharedMemorySize, SMEM_TOTAL);

    init_kernel<<<1, 1>>>();
    prep_z<<<NROWS / 8, 256>>>(z);
    prep_cb<<<KCODES / 8, 256>>>(cb);
    vq_approx<<<NROWS / BM, 512, SMEM_TOTAL>>>();
    vq_rescore<<<NROWS / 8, 256>>>(z, cb, zq_out, ids_out);
    finalize_kernel<<<1, 1>>>(loss_out);
}